// round 16
// baseline (speedup 1.0000x reference)
#include <cuda_runtime.h>
#include <cuda_fp16.h>
#include <math.h>
#include <stdint.h>

#define NROWS 8192
#define CDIM  512
#define EDIM  256
#define HDIM  1024
#define CHUNK 128
#define NCHUNK (NROWS / CHUNK)   // 64
#define NSLICE 8                 // rank slices
#define KBINS  (NROWS + 1)

// ================= helpers =================
__device__ __forceinline__ uint32_t smem_u32(const void* p) {
    uint32_t a;
    asm("{ .reg .u64 t; cvta.to.shared.u64 t, %1; cvt.u32.u64 %0, t; }" : "=r"(a) : "l"(p));
    return a;
}
#define CP_ASYNC(dst, src) \
    asm volatile("cp.async.cg.shared.global [%0], [%1], 16;" :: "r"(dst), "l"(src) : "memory")
#define CP_COMMIT() asm volatile("cp.async.commit_group;" ::: "memory")
#define CP_WAIT1()  asm volatile("cp.async.wait_group 1;" ::: "memory")
#define CP_WAIT0()  asm volatile("cp.async.wait_group 0;" ::: "memory")

#define LDMX4(r0, r1, r2, r3, a) \
    asm volatile("ldmatrix.sync.aligned.m8n8.x4.shared.b16 {%0,%1,%2,%3}, [%4];" \
        : "=r"(r0), "=r"(r1), "=r"(r2), "=r"(r3) : "r"(a))

#define MMA_F16(d, a, b0, b1) \
    asm volatile("mma.sync.aligned.m16n8k16.row.col.f32.f16.f16.f32 " \
        "{%0,%1,%2,%3}, {%4,%5,%6,%7}, {%8,%9}, {%0,%1,%2,%3};" \
        : "+f"((d)[0]), "+f"((d)[1]), "+f"((d)[2]), "+f"((d)[3]) \
        : "r"((a)[0]), "r"((a)[1]), "r"((a)[2]), "r"((a)[3]), "r"(b0), "r"(b1))

__device__ __forceinline__ uint2 pack4h(float x, float y, float z, float w)
{
    __half2 H0 = __halves2half2(__float2half_rn(x), __float2half_rn(y));
    __half2 H1 = __halves2half2(__float2half_rn(z), __float2half_rn(w));
    uint2 H; H.x = *(uint32_t*)&H0; H.y = *(uint32_t*)&H1;
    return H;
}

// ================= scratch =================
__device__ float g_xe [NROWS * CDIM];
__device__ float g_h  [NROWS * HDIM];
__device__ float g_s1 [2][NROWS];
__device__ float g_s2 [2][NROWS];
__device__ float g_sorted[2][NROWS];
__device__ int   g_perm  [2][NROWS];
__device__ float g_wpos  [2][NROWS];
__device__ float g_wneg  [2][NROWS];
__device__ int   g_rankpart[2][NSLICE][NROWS];
__device__ float g_cpos[2][NCHUNK * CDIM];
__device__ float g_cneg[2][NCHUNK * CDIM];
__device__ float g_offp[2][NCHUNK * CDIM];
__device__ float g_offn[2][NCHUNK * CDIM];
__device__ float g_zcp[2][NCHUNK], g_zcn[2][NCHUNK];
__device__ float g_zoffp[2][NCHUNK], g_zoffn[2][NCHUNK];
// k-bucket machinery (validated in R13)
__device__ int g_krow   [2][NROWS];
__device__ int g_kcnt   [2][KBINS];
__device__ int g_kpre   [2][KBINS + 1];
__device__ int g_koff   [2][KBINS];
__device__ int g_roworder[2][NROWS];
__device__ int g_pord   [2][NROWS];
// fp16 buffers
__device__ __half g_enc_h [NROWS * EDIM];
__device__ __half g_wenc_h[CDIM * EDIM];
__device__ __half g_xn_h  [NROWS * CDIM];
__device__ __half g_att_h [2][NROWS * CDIM];   // v then (in-place) LN2(v)
__device__ __half g_w0_h  [HDIM * CDIM];
__device__ __half g_w1_h  [2 * CDIM * CDIM];

// ================= merged conversion =================
#define N4_ENC  (NROWS * EDIM / 4)
#define N4_WENC (CDIM * EDIM / 4)
#define N4_W0   (HDIM * CDIM / 4)
#define N4_W1   (2 * CDIM * CDIM / 4)
#define N4_ALL  (N4_ENC + N4_WENC + N4_W0 + N4_W1)

__global__ __launch_bounds__(256)
void convert_all(const float* __restrict__ enc, const float* __restrict__ wenc,
                 const float* __restrict__ w0, const float* __restrict__ w1)
{
    int i = blockIdx.x * 256 + threadIdx.x;
    if (i >= N4_ALL) return;
    const float* src;
    __half* dst;
    int off;
    if (i < N4_ENC) {
        src = enc; dst = g_enc_h; off = i;
    } else if (i < N4_ENC + N4_WENC) {
        src = wenc; dst = g_wenc_h; off = i - N4_ENC;
    } else if (i < N4_ENC + N4_WENC + N4_W0) {
        src = w0; dst = g_w0_h; off = i - N4_ENC - N4_WENC;
    } else {
        src = w1; dst = g_w1_h; off = i - N4_ENC - N4_WENC - N4_W0;
    }
    float4 v = ((const float4*)src)[off];
    ((uint2*)dst)[off] = pack4h(v.x, v.y, v.z, v.w);
}

// ================= fp16 GEMM: CTA 128x256, 512 threads, warp 64x32 =============
#define PADB    144
#define MAT_A   (128 * PADB)
#define MAT_Bt  (256 * PADB)
#define STAGE_B (MAT_A + MAT_Bt)
#define NSTAGE  3
#define SMEM_GEMM (NSTAGE * STAGE_B)

__global__ __launch_bounds__(512, 1)
void gemm_f16(const __half* __restrict__ Ahi, const __half* __restrict__ Bhi,
              float* __restrict__ Cmat, int M, int N, int K, int mode,
              const float* __restrict__ addmat, const float* __restrict__ bias, float scale,
              int nrep, const __half* __restrict__ Ahi2, const __half* __restrict__ Bhi2)
{
    extern __shared__ char smem[];
    const uint32_t sb = smem_u32(smem);
    const int tid = threadIdx.x;
    const int lane = tid & 31;
    const int wid = tid >> 5;
    const int warp_m = wid & 1;
    const int warp_n = wid >> 1;
    const int by = blockIdx.y;

    const int npass = (Ahi2 != nullptr) ? 2 : nrep;
    const int NP = K >> 6;
    const int lr = lane & 7, lsub = lane >> 3;
    const int a_moff = (lsub & 1) * 8 + lr;
    const int a_ksub = lsub >> 1;
    const int b_noff = (lsub >> 1) * 8 + lr;
    const int b_ksub = lsub & 1;

    for (int pass = 0; pass < npass; pass++) {
        const __half* A = (Ahi2 && pass) ? Ahi2 : Ahi;
        const __half* B = (Ahi2 && pass) ? Bhi2 : Bhi;
        const int emode = (Ahi2 && pass) ? 3 : mode;
        const int n0 = (Ahi2 ? blockIdx.x : (blockIdx.x * nrep + pass)) * 256;
        if (pass) __syncthreads();

#define ISSUE_STAGE(s) do { \
    const uint32_t _st = sb + (uint32_t)((s) % NSTAGE) * STAGE_B; \
    const size_t _ko = (size_t)(s) * 64; \
    _Pragma("unroll") \
    for (int j = 0; j < 2; j++) { \
        const int idx = j * 512 + tid; \
        const int row = idx >> 3, col = idx & 7; \
        CP_ASYNC(_st + row * PADB + col * 16, \
                 A + (size_t)(by * 128 + row) * K + _ko + col * 8); \
    } \
    _Pragma("unroll") \
    for (int j = 0; j < 4; j++) { \
        const int idx = j * 512 + tid; \
        const int row = idx >> 3, col = idx & 7; \
        CP_ASYNC(_st + MAT_A + row * PADB + col * 16, \
                 B + (size_t)(n0 + row) * K + _ko + col * 8); \
    } \
    CP_COMMIT(); \
} while (0)

        ISSUE_STAGE(0);
        if (NP > 1) ISSUE_STAGE(1);

        float acc[4][4][4];
#pragma unroll
        for (int i = 0; i < 4; i++)
#pragma unroll
            for (int j = 0; j < 4; j++)
#pragma unroll
                for (int q = 0; q < 4; q++) acc[i][j][q] = 0.f;

        for (int i = 0; i < NP; i++) {
            if (i + 1 < NP) CP_WAIT1(); else CP_WAIT0();
            __syncthreads();
            if (i + 2 < NP) ISSUE_STAGE(i + 2);

            const uint32_t st = sb + (uint32_t)(i % NSTAGE) * STAGE_B;
#pragma unroll
            for (int ks = 0; ks < 4; ks++) {
                const int kc = ks * 2;
                uint32_t bh[2][4];
#pragma unroll
                for (int p = 0; p < 2; p++) {
                    uint32_t addr = st + MAT_A
                        + (uint32_t)(warp_n * 32 + p * 16 + b_noff) * PADB
                        + (uint32_t)(kc + b_ksub) * 16;
                    LDMX4(bh[p][0], bh[p][1], bh[p][2], bh[p][3], addr);
                }
#pragma unroll
                for (int mi = 0; mi < 4; mi++) {
                    uint32_t ah[4];
                    uint32_t addr = st
                        + (uint32_t)(warp_m * 64 + mi * 16 + a_moff) * PADB
                        + (uint32_t)(kc + a_ksub) * 16;
                    LDMX4(ah[0], ah[1], ah[2], ah[3], addr);
#pragma unroll
                    for (int p = 0; p < 2; p++) {
#pragma unroll
                        for (int q = 0; q < 2; q++) {
                            MMA_F16(acc[mi][p * 2 + q], ah, bh[p][q * 2], bh[p][q * 2 + 1]);
                        }
                    }
                }
            }
        }
#undef ISSUE_STAGE

        const int mbase = by * 128 + warp_m * 64 + (lane >> 2);
        const int nbase = n0 + warp_n * 32 + (lane & 3) * 2;
#pragma unroll
        for (int mi = 0; mi < 4; mi++) {
#pragma unroll
            for (int ni = 0; ni < 4; ni++) {
                const int n = nbase + ni * 8;
#pragma unroll
                for (int half = 0; half < 2; half++) {
                    const int m = mbase + mi * 16 + half * 8;
                    float vx = acc[mi][ni][half * 2 + 0];
                    float vy = acc[mi][ni][half * 2 + 1];
                    const size_t idx = (size_t)m * N + n;
                    if (emode == 1) {
                        float2 a = *(const float2*)(addmat + idx);
                        vx += a.x + bias[n];
                        vy += a.y + bias[n + 1];
                    } else if (emode >= 2) {
                        vx = ((vx > 0.f) ? vx : expm1f(vx)) * scale;
                        vy = ((vy > 0.f) ? vy : expm1f(vy)) * scale;
                        if (emode == 3) {
                            float2 c = *(const float2*)(Cmat + idx);
                            vx += c.x; vy += c.y;
                        }
                    }
                    float2 o; o.x = vx; o.y = vy;
                    *(float2*)(Cmat + idx) = o;
                }
            }
        }
    }
}

// ================= row LayerNorm -> fp16 hi =================
__global__ __launch_bounds__(128)
void ln_kernel(const float* __restrict__ in, __half* __restrict__ hi,
               const float* __restrict__ g, const float* __restrict__ b)
{
    const int row = blockIdx.x;
    const int tid = threadIdx.x;
    const int c = tid * 4;
    float4 v = *(const float4*)(in + (size_t)row * CDIM + c);
    float s  = v.x + v.y + v.z + v.w;
    float ss = v.x * v.x + v.y * v.y + v.z * v.z + v.w * v.w;
    __shared__ float rs[4], rss[4];
#pragma unroll
    for (int o = 16; o; o >>= 1) {
        s  += __shfl_down_sync(0xffffffffu, s,  o);
        ss += __shfl_down_sync(0xffffffffu, ss, o);
    }
    if ((tid & 31) == 0) { rs[tid >> 5] = s; rss[tid >> 5] = ss; }
    __syncthreads();
    float S  = rs[0] + rs[1] + rs[2] + rs[3];
    float SS = rss[0] + rss[1] + rss[2] + rss[3];
    float mu  = S * (1.f / CDIM);
    float var = SS * (1.f / CDIM) - mu * mu;
    float inv = rsqrtf(var + 1e-5f);
    float4 gv = *(const float4*)(g + c);
    float4 bv = *(const float4*)(b + c);
    ((uint2*)(hi + (size_t)row * CDIM))[tid] = pack4h(
        (v.x - mu) * inv * gv.x + bv.x,
        (v.y - mu) * inv * gv.y + bv.y,
        (v.z - mu) * inv * gv.z + bv.z,
        (v.w - mu) * inv * gv.w + bv.w);
}

// ================= s1/s2 =================
__global__ void s_kernel(const float* __restrict__ Wa)
{
    const int head = blockIdx.y;
    const int row = blockIdx.x * 8 + threadIdx.y;
    const int lane = threadIdx.x;
    const float* hr = g_h + (size_t)row * HDIM + head * CDIM;
    const float* wa = Wa + head * 2 * CDIM;
    float a = 0.f, bv = 0.f;
#pragma unroll
    for (int t = 0; t < 16; t++) {
        int c = lane + 32 * t;
        float hv = hr[c];
        a  = fmaf(hv, wa[c], a);
        bv = fmaf(hv, wa[CDIM + c], bv);
    }
#pragma unroll
    for (int o = 16; o; o >>= 1) {
        a  += __shfl_down_sync(0xffffffffu, a,  o);
        bv += __shfl_down_sync(0xffffffffu, bv, o);
    }
    if (lane == 0) { g_s1[head][row] = a; g_s2[head][row] = bv; }
}

// ================= rank phase 1 =================
__global__ __launch_bounds__(256)
void partial_rank_kernel()
{
    const int head = blockIdx.z;
    const int sl   = blockIdx.y;
    __shared__ float4 sh[256];
    sh[threadIdx.x] = ((const float4*)g_s2[head])[sl * 256 + threadIdx.x];
    __syncthreads();
    const int i = blockIdx.x * 256 + threadIdx.x;
    const float v = g_s2[head][i];
    int r = 0;
#pragma unroll 4
    for (int jj = 0; jj < 256; jj++) {
        float4 u = sh[jj];
        const int j = sl * 1024 + jj * 4;
        r += (u.x < v) || (u.x == v && j + 0 < i);
        r += (u.y < v) || (u.y == v && j + 1 < i);
        r += (u.z < v) || (u.z == v && j + 2 < i);
        r += (u.w < v) || (u.w == v && j + 3 < i);
    }
    g_rankpart[head][sl][i] = r;
}

// ================= rank phase 2 =================
__global__ __launch_bounds__(256)
void scatter_kernel()
{
    const int head = blockIdx.y;
    const int i = blockIdx.x * 256 + threadIdx.x;
    int r = 0;
#pragma unroll
    for (int sl = 0; sl < NSLICE; sl++) r += g_rankpart[head][sl][i];
    const float v = g_s2[head][i];
    g_sorted[head][r] = v;
    g_perm[head][r]   = i;
    g_wpos[head][r]   = expf(v);
    g_wneg[head][r]   = expf(0.01f * v);
}

// ================= k-bucket kernels (validated R13) =================
__global__ __launch_bounds__(256)
void zero_kcnt_kernel()
{
    int i = blockIdx.x * 256 + threadIdx.x;
    if (i < 2 * KBINS) ((int*)g_kcnt)[i] = 0;
}

__global__ __launch_bounds__(256)
void ksearch_kernel()
{
    const int head = blockIdx.y;
    const int i = blockIdx.x * 256 + threadIdx.x;
    const float thr = -g_s1[head][i];
    int lo = 0, hi = NROWS;
    while (lo < hi) {
        int mid = (lo + hi) >> 1;
        if (g_sorted[head][mid] <= thr) lo = mid + 1; else hi = mid;
    }
    g_krow[head][i] = lo;
    atomicAdd(&g_kcnt[head][lo], 1);
}

#define SEG 9
__global__ __launch_bounds__(1024)
void kprefix_kernel()
{
    const int head = blockIdx.x;
    const int tid = threadIdx.x;
    const int lane = tid & 31, wid = tid >> 5;
    int vals[SEG];
    int sum = 0;
#pragma unroll
    for (int j = 0; j < SEG; j++) {
        int m = tid * SEG + j;
        int cv = (m < KBINS) ? g_kcnt[head][m] : 0;
        vals[j] = sum;
        sum += cv;
    }
    int incl = sum;
#pragma unroll
    for (int o = 1; o < 32; o <<= 1) {
        int n = __shfl_up_sync(0xffffffffu, incl, o);
        if (lane >= o) incl += n;
    }
    __shared__ int wsum[32];
    if (lane == 31) wsum[wid] = incl;
    __syncthreads();
    if (wid == 0) {
        int w = wsum[lane];
#pragma unroll
        for (int o = 1; o < 32; o <<= 1) {
            int n = __shfl_up_sync(0xffffffffu, w, o);
            if (lane >= o) w += n;
        }
        wsum[lane] = w;
    }
    __syncthreads();
    int base = incl - sum + (wid > 0 ? wsum[wid - 1] : 0);
#pragma unroll
    for (int j = 0; j < SEG; j++) {
        int m = tid * SEG + j;
        if (m <= KBINS) {
            int pre = base + vals[j];
            g_kpre[head][m] = pre;
            if (m < KBINS) g_koff[head][m] = pre;
        }
    }
}

__global__ __launch_bounds__(256)
void korder_kernel()
{
    const int head = blockIdx.y;
    const int i = blockIdx.x * 256 + threadIdx.x;
    const int k = g_krow[head][i];
    const int slot = atomicAdd(&g_koff[head][k], 1);
    g_roworder[head][slot] = i;
    g_pord[head][slot] = k;
}

// ================= chunked scan: phase 1 =================
__global__ __launch_bounds__(128)
void chunk_sum_kernel()
{
    const int s = blockIdx.x, c = blockIdx.y, head = blockIdx.z;
    const int col = s * 128 + threadIdx.x;
    const int u0 = c * CHUNK;
    float accp = 0.f, accn = 0.f;
    float zp = 0.f, zn = 0.f;
    const bool do_z = (s == 0 && threadIdx.x == 0);
#pragma unroll 4
    for (int t = 0; t < CHUNK; t++) {
        const int u = u0 + t;
        const int r = g_perm[head][u];
        const float wp = g_wpos[head][u], wn = g_wneg[head][u];
        const float hv = g_h[(size_t)r * HDIM + head * CDIM + col];
        accp = fmaf(wp, hv, accp);
        accn = fmaf(wn, hv, accn);
        if (do_z) { zp += wp; zn += wn; }
    }
    g_cpos[head][c * CDIM + col] = accp;
    g_cneg[head][c * CDIM + col] = accn;
    if (do_z) { g_zcp[head][c] = zp; g_zcn[head][c] = zn; }
}

// ================= chunked scan: phase 2 (prefetch-8) =================
__global__ __launch_bounds__(512)
void chunk_scan_kernel()
{
    const int head = blockIdx.x;
    const int col = threadIdx.x;
    {
        float run = 0.f;
        for (int c0 = 0; c0 < NCHUNK; c0 += 8) {
            float v[8];
#pragma unroll
            for (int j = 0; j < 8; j++) v[j] = g_cneg[head][(c0 + j) * CDIM + col];
#pragma unroll
            for (int j = 0; j < 8; j++) {
                g_offn[head][(c0 + j) * CDIM + col] = run;
                run += v[j];
            }
        }
    }
    {
        float run = 0.f;
        for (int c0 = NCHUNK - 8; c0 >= 0; c0 -= 8) {
            float v[8];
#pragma unroll
            for (int j = 0; j < 8; j++) v[j] = g_cpos[head][(c0 + j) * CDIM + col];
#pragma unroll
            for (int j = 7; j >= 0; j--) {
                g_offp[head][(c0 + j) * CDIM + col] = run;
                run += v[j];
            }
        }
    }
    if (col == 0) {
        float zr = 0.f;
        for (int c = 0; c < NCHUNK; c++) { g_zoffn[head][c] = zr; zr += g_zcn[head][c]; }
    } else if (col == 1) {
        float zr = 0.f;
        for (int c = NCHUNK - 1; c >= 0; c--) { g_zoffp[head][c] = zr; zr += g_zcp[head][c]; }
    }
}

// ================= barrier-free fused scan + attention emit ====================
// One block per (chunk, head), 512 threads = 1 col each.
// zrn/zrp are identical in every thread -> ap/an/inv_den computed per thread,
// no cross-thread communication in an emission. LN2 deferred to ln2_kernel.
#define PF 8
__global__ __launch_bounds__(512)
void emit_kernel()
{
    const int c = blockIdx.x, head = blockIdx.y;
    const int tid = threadIdx.x;
    const int u0 = c * CHUNK;

    __shared__ float swn[CHUNK], swp[CHUNK];
    __shared__ int   sperm[CHUNK];

    if (tid < CHUNK) {
        swn[tid] = g_wneg[head][u0 + tid];
        swp[tid] = g_wpos[head][u0 + tid];
        sperm[tid] = g_perm[head][u0 + tid];
    }
    __syncthreads();

    const float offn_c  = g_offn[head][c * CDIM + tid];
    const float sufb_c  = g_offp[head][c * CDIM + tid] + g_cpos[head][c * CDIM + tid];
    const float zoffn_c = g_zoffn[head][c];
    const float zsufb_c = g_zoffp[head][c] + g_zcp[head][c];

    float runn = 0.f, runp = 0.f;
    float zrn = 0.f, zrp = 0.f;

    const int lo = g_kpre[head][u0];
    const int hi = g_kpre[head][(c == NCHUNK - 1) ? KBINS : (u0 + CHUNK)];

    int ptr = lo;
    int row_cur = 0, p_cur = CHUNK + 1;
    float xe_cur = 0.f, s1_cur = 0.f;
    if (ptr < hi) {
        row_cur = g_roworder[head][ptr];
        p_cur = g_pord[head][ptr] - u0;
        xe_cur = g_xe[(size_t)row_cur * CDIM + tid];
        s1_cur = g_s1[head][row_cur];
    }

    float hbuf[PF];
#pragma unroll
    for (int j = 0; j < PF; j++)
        hbuf[j] = g_h[(size_t)sperm[j] * HDIM + head * CDIM + tid];

    for (int t = 0; t <= CHUNK; t++) {
        while (ptr < hi && p_cur == t) {
            // prefetch next emission
            int row_nxt = 0, p_nxt = CHUNK + 1;
            float xe_nxt = 0.f, s1_nxt = 0.f;
            if (ptr + 1 < hi) {
                row_nxt = g_roworder[head][ptr + 1];
                p_nxt = g_pord[head][ptr + 1] - u0;
                xe_nxt = g_xe[(size_t)row_nxt * CDIM + tid];
                s1_nxt = g_s1[head][row_nxt];
            }
            // all quantities per-thread; no barriers
            const float ap = expf(s1_cur);
            const float an = expf(0.01f * s1_cur);
            const float inv_den = 1.f / (ap * (zsufb_c - zrp) + an * (zoffn_c + zrn));
            const float v = (ap * (sufb_c - runp) + an * (offn_c + runn)) * inv_den + xe_cur;
            g_att_h[head][(size_t)row_cur * CDIM + tid] = __float2half_rn(v);
            ptr++;
            row_cur = row_nxt; p_cur = p_nxt; xe_cur = xe_nxt; s1_cur = s1_nxt;
        }
        if (t < CHUNK) {
            const float hv = hbuf[t % PF];
            if (t + PF < CHUNK)
                hbuf[t % PF] = g_h[(size_t)sperm[t + PF] * HDIM + head * CDIM + tid];
            runn = fmaf(swn[t], hv, runn);
            runp = fmaf(swp[t], hv, runp);
            zrn += swn[t];
            zrp += swp[t];
        }
    }
}

// ================= LN2 in place over att_h (both heads per block) ==============
__global__ __launch_bounds__(128)
void ln2_kernel(const float* __restrict__ ln2g, const float* __restrict__ ln2b)
{
    const int row = blockIdx.x;
    const int tid = threadIdx.x;
    const int c = tid * 4;
    __shared__ float rs[4], rss[4];
    float4 gv = *(const float4*)(ln2g + c);
    float4 bv = *(const float4*)(ln2b + c);

#pragma unroll
    for (int head = 0; head < 2; head++) {
        uint2 vu = ((const uint2*)(g_att_h[head] + (size_t)row * CDIM))[tid];
        float2 v0 = __half22float2(*(__half2*)&vu.x);
        float2 v1 = __half22float2(*(__half2*)&vu.y);
        float s  = v0.x + v0.y + v1.x + v1.y;
        float ss = v0.x * v0.x + v0.y * v0.y + v1.x * v1.x + v1.y * v1.y;
#pragma unroll
        for (int o = 16; o; o >>= 1) {
            s  += __shfl_down_sync(0xffffffffu, s,  o);
            ss += __shfl_down_sync(0xffffffffu, ss, o);
        }
        if ((tid & 31) == 0) { rs[tid >> 5] = s; rss[tid >> 5] = ss; }
        __syncthreads();
        float S  = rs[0] + rs[1] + rs[2] + rs[3];
        float SS = rss[0] + rss[1] + rss[2] + rss[3];
        float mu  = S * (1.f / CDIM);
        float var = SS * (1.f / CDIM) - mu * mu;
        float inv = rsqrtf(var + 1e-5f);
        ((uint2*)(g_att_h[head] + (size_t)row * CDIM))[tid] = pack4h(
            (v0.x - mu) * inv * gv.x + bv.x,
            (v0.y - mu) * inv * gv.y + bv.y,
            (v1.x - mu) * inv * gv.z + bv.z,
            (v1.y - mu) * inv * gv.w + bv.w);
        __syncthreads();
    }
}

// ================= launch =================
extern "C" void kernel_launch(void* const* d_in, const int* in_sizes, int n_in,
                              void* d_out, int out_size)
{
    const float* x     = (const float*)d_in[0];
    const float* enc   = (const float*)d_in[1];
    const float* W_enc = (const float*)d_in[2];
    const float* b_enc = (const float*)d_in[3];
    const float* ln1g  = (const float*)d_in[4];
    const float* ln1b  = (const float*)d_in[5];
    const float* ln2g  = (const float*)d_in[6];
    const float* ln2b  = (const float*)d_in[7];
    const float* W0    = (const float*)d_in[8];
    const float* W1    = (const float*)d_in[9];
    const float* Wa    = (const float*)d_in[10];
    float* out = (float*)d_out;

    static int attr_done = 0;
    if (!attr_done) {
        cudaFuncSetAttribute(gemm_f16, cudaFuncAttributeMaxDynamicSharedMemorySize, SMEM_GEMM);
        attr_done = 1;
    }

    void *p_xe, *p_h;
    cudaGetSymbolAddress(&p_xe, g_xe);
    cudaGetSymbolAddress(&p_h,  g_h);
    float* xe = (float*)p_xe;
    float* h  = (float*)p_h;

    void *p_ench, *p_wench, *p_xnh, *p_atth, *p_w0h, *p_w1h;
    cudaGetSymbolAddress(&p_ench,  g_enc_h);
    cudaGetSymbolAddress(&p_wench, g_wenc_h);
    cudaGetSymbolAddress(&p_xnh,   g_xn_h);
    cudaGetSymbolAddress(&p_atth,  g_att_h);
    cudaGetSymbolAddress(&p_w0h,   g_w0_h);
    cudaGetSymbolAddress(&p_w1h,   g_w1_h);
    __half* ench  = (__half*)p_ench;
    __half* wench = (__half*)p_wench;
    __half* xnh   = (__half*)p_xnh;
    __half* atth  = (__half*)p_atth;
    __half* w0h   = (__half*)p_w0h;
    __half* w1h   = (__half*)p_w1h;

    dim3 ggrid(2, NROWS / 128);             // (2, 64) = 128 CTAs
    dim3 scan_grid(CDIM / 128, NCHUNK, 2);

    convert_all<<<(N4_ALL + 255) / 256, 256>>>(enc, W_enc, W0, W1);

    // 1) xe = x + enc @ W_enc^T + b_enc
    gemm_f16<<<ggrid, 512, SMEM_GEMM>>>(ench, wench, xe,
                                        NROWS, CDIM, EDIM, 1, x, b_enc, 1.f,
                                        1, nullptr, nullptr);
    // 2) xn = LN1(xe)
    ln_kernel<<<NROWS, 128>>>(xe, xnh, ln1g, ln1b);

    // 3) h_both = xn @ [W0_0; W0_1]^T
    gemm_f16<<<ggrid, 512, SMEM_GEMM>>>(xnh, w0h, h,
                                        NROWS, HDIM, CDIM, 0, nullptr, nullptr, 1.f,
                                        2, nullptr, nullptr);

    // 4) attention pipeline (both heads)
    s_kernel<<<dim3(NROWS / 8, 2), dim3(32, 8)>>>(Wa);
    partial_rank_kernel<<<dim3(NROWS / 256, NSLICE, 2), 256>>>();
    scatter_kernel<<<dim3(NROWS / 256, 2), 256>>>();
    zero_kcnt_kernel<<<(2 * KBINS + 255) / 256, 256>>>();
    ksearch_kernel<<<dim3(NROWS / 256, 2), 256>>>();
    kprefix_kernel<<<2, 1024>>>();
    korder_kernel<<<dim3(NROWS / 256, 2), 256>>>();
    chunk_sum_kernel<<<scan_grid, 128>>>();
    chunk_scan_kernel<<<2, 512>>>();
    emit_kernel<<<dim3(NCHUNK, 2), 512>>>();
    ln2_kernel<<<NROWS, 128>>>(ln2g, ln2b);

    // 5) out = elu(att0 @ W1_0^T)/2 + elu(att1 @ W1_1^T)/2
    gemm_f16<<<ggrid, 512, SMEM_GEMM>>>(atth, w1h, out,
                                        NROWS, CDIM, CDIM, 2, nullptr, nullptr, 0.5f,
                                        1, atth + (size_t)NROWS * CDIM,
                                        w1h + (size_t)CDIM * CDIM);
}

// round 17
// speedup vs baseline: 1.3547x; 1.3547x over previous
#include <cuda_runtime.h>
#include <cuda_fp16.h>
#include <math.h>
#include <stdint.h>

#define NROWS 8192
#define CDIM  512
#define EDIM  256
#define HDIM  1024
#define CHUNK 128
#define NCHUNK (NROWS / CHUNK)   // 64
#define NSLICE 8                 // rank slices

// ================= helpers =================
__device__ __forceinline__ uint32_t smem_u32(const void* p) {
    uint32_t a;
    asm("{ .reg .u64 t; cvta.to.shared.u64 t, %1; cvt.u32.u64 %0, t; }" : "=r"(a) : "l"(p));
    return a;
}
#define CP_ASYNC(dst, src) \
    asm volatile("cp.async.cg.shared.global [%0], [%1], 16;" :: "r"(dst), "l"(src) : "memory")
#define CP_COMMIT() asm volatile("cp.async.commit_group;" ::: "memory")
#define CP_WAIT1()  asm volatile("cp.async.wait_group 1;" ::: "memory")
#define CP_WAIT0()  asm volatile("cp.async.wait_group 0;" ::: "memory")

#define LDMX4(r0, r1, r2, r3, a) \
    asm volatile("ldmatrix.sync.aligned.m8n8.x4.shared.b16 {%0,%1,%2,%3}, [%4];" \
        : "=r"(r0), "=r"(r1), "=r"(r2), "=r"(r3) : "r"(a))

#define MMA_F16(d, a, b0, b1) \
    asm volatile("mma.sync.aligned.m16n8k16.row.col.f32.f16.f16.f32 " \
        "{%0,%1,%2,%3}, {%4,%5,%6,%7}, {%8,%9}, {%0,%1,%2,%3};" \
        : "+f"((d)[0]), "+f"((d)[1]), "+f"((d)[2]), "+f"((d)[3]) \
        : "r"((a)[0]), "r"((a)[1]), "r"((a)[2]), "r"((a)[3]), "r"(b0), "r"(b1))

__device__ __forceinline__ uint2 pack4h(float x, float y, float z, float w)
{
    __half2 H0 = __halves2half2(__float2half_rn(x), __float2half_rn(y));
    __half2 H1 = __halves2half2(__float2half_rn(z), __float2half_rn(w));
    uint2 H; H.x = *(uint32_t*)&H0; H.y = *(uint32_t*)&H1;
    return H;
}

// ================= scratch =================
__device__ float g_xe [NROWS * CDIM];
__device__ float g_h  [NROWS * HDIM];
__device__ float g_s1 [2][NROWS];
__device__ float g_s2 [2][NROWS];
__device__ float g_sorted[2][NROWS];
__device__ int   g_perm  [2][NROWS];
__device__ float g_wpos  [2][NROWS];
__device__ float g_wneg  [2][NROWS];
__device__ int   g_rankpart[2][NSLICE][NROWS];
// local (per-chunk) exclusive prefixes, fp16; index k in [0, NROWS]
__device__ __half g_Pneg16[2][(NROWS + 1) * CDIM];
__device__ __half g_Ppos16[2][(NROWS + 1) * CDIM];
__device__ float g_Zpn[2][NROWS + 1];    // local z prefixes (wneg)
__device__ float g_Zpp[2][NROWS + 1];    // local z prefixes (wpos)
// chunk totals + offsets (65 chunk entries for offsets)
__device__ float g_cpos[2][NCHUNK * CDIM];
__device__ float g_cneg[2][NCHUNK * CDIM];
__device__ float g_offn [2][(NCHUNK + 1) * CDIM];  // excl prefix of cneg
__device__ float g_offp2[2][(NCHUNK + 1) * CDIM];  // incl suffix of cpos
__device__ float g_zcp[2][NCHUNK], g_zcn[2][NCHUNK];
__device__ float g_zoffn[2][NCHUNK + 1], g_zoffp2[2][NCHUNK + 1];
// fp16 buffers (hi only)
__device__ __half g_enc_h [NROWS * EDIM];
__device__ __half g_wenc_h[CDIM * EDIM];
__device__ __half g_xn_h  [NROWS * CDIM];
__device__ __half g_att_h [2][NROWS * CDIM];
__device__ __half g_w0_h  [HDIM * CDIM];
__device__ __half g_w1_h  [2 * CDIM * CDIM];

// ================= merged conversion =================
#define N4_ENC  (NROWS * EDIM / 4)
#define N4_WENC (CDIM * EDIM / 4)
#define N4_W0   (HDIM * CDIM / 4)
#define N4_W1   (2 * CDIM * CDIM / 4)
#define N4_ALL  (N4_ENC + N4_WENC + N4_W0 + N4_W1)

__global__ __launch_bounds__(256)
void convert_all(const float* __restrict__ enc, const float* __restrict__ wenc,
                 const float* __restrict__ w0, const float* __restrict__ w1)
{
    int i = blockIdx.x * 256 + threadIdx.x;
    if (i >= N4_ALL) return;
    const float* src;
    __half* dst;
    int off;
    if (i < N4_ENC) {
        src = enc; dst = g_enc_h; off = i;
    } else if (i < N4_ENC + N4_WENC) {
        src = wenc; dst = g_wenc_h; off = i - N4_ENC;
    } else if (i < N4_ENC + N4_WENC + N4_W0) {
        src = w0; dst = g_w0_h; off = i - N4_ENC - N4_WENC;
    } else {
        src = w1; dst = g_w1_h; off = i - N4_ENC - N4_WENC - N4_W0;
    }
    float4 v = ((const float4*)src)[off];
    ((uint2*)dst)[off] = pack4h(v.x, v.y, v.z, v.w);
}

// ================= fp16 GEMM: CTA 128x256, 512 threads, warp 64x32 =============
#define PADB    144
#define MAT_A   (128 * PADB)
#define MAT_Bt  (256 * PADB)
#define STAGE_B (MAT_A + MAT_Bt)
#define NSTAGE  3
#define SMEM_GEMM (NSTAGE * STAGE_B)

__global__ __launch_bounds__(512, 1)
void gemm_f16(const __half* __restrict__ Ahi, const __half* __restrict__ Bhi,
              float* __restrict__ Cmat, int M, int N, int K, int mode,
              const float* __restrict__ addmat, const float* __restrict__ bias, float scale,
              int nrep, const __half* __restrict__ Ahi2, const __half* __restrict__ Bhi2)
{
    extern __shared__ char smem[];
    const uint32_t sb = smem_u32(smem);
    const int tid = threadIdx.x;
    const int lane = tid & 31;
    const int wid = tid >> 5;
    const int warp_m = wid & 1;
    const int warp_n = wid >> 1;
    const int by = blockIdx.y;

    const int npass = (Ahi2 != nullptr) ? 2 : nrep;
    const int NP = K >> 6;
    const int lr = lane & 7, lsub = lane >> 3;
    const int a_moff = (lsub & 1) * 8 + lr;
    const int a_ksub = lsub >> 1;
    const int b_noff = (lsub >> 1) * 8 + lr;
    const int b_ksub = lsub & 1;

    for (int pass = 0; pass < npass; pass++) {
        const __half* A = (Ahi2 && pass) ? Ahi2 : Ahi;
        const __half* B = (Ahi2 && pass) ? Bhi2 : Bhi;
        const int emode = (Ahi2 && pass) ? 3 : mode;
        const int n0 = (Ahi2 ? blockIdx.x : (blockIdx.x * nrep + pass)) * 256;
        if (pass) __syncthreads();

#define ISSUE_STAGE(s) do { \
    const uint32_t _st = sb + (uint32_t)((s) % NSTAGE) * STAGE_B; \
    const size_t _ko = (size_t)(s) * 64; \
    _Pragma("unroll") \
    for (int j = 0; j < 2; j++) { \
        const int idx = j * 512 + tid; \
        const int row = idx >> 3, col = idx & 7; \
        CP_ASYNC(_st + row * PADB + col * 16, \
                 A + (size_t)(by * 128 + row) * K + _ko + col * 8); \
    } \
    _Pragma("unroll") \
    for (int j = 0; j < 4; j++) { \
        const int idx = j * 512 + tid; \
        const int row = idx >> 3, col = idx & 7; \
        CP_ASYNC(_st + MAT_A + row * PADB + col * 16, \
                 B + (size_t)(n0 + row) * K + _ko + col * 8); \
    } \
    CP_COMMIT(); \
} while (0)

        ISSUE_STAGE(0);
        if (NP > 1) ISSUE_STAGE(1);

        float acc[4][4][4];
#pragma unroll
        for (int i = 0; i < 4; i++)
#pragma unroll
            for (int j = 0; j < 4; j++)
#pragma unroll
                for (int q = 0; q < 4; q++) acc[i][j][q] = 0.f;

        for (int i = 0; i < NP; i++) {
            if (i + 1 < NP) CP_WAIT1(); else CP_WAIT0();
            __syncthreads();
            if (i + 2 < NP) ISSUE_STAGE(i + 2);

            const uint32_t st = sb + (uint32_t)(i % NSTAGE) * STAGE_B;
#pragma unroll
            for (int ks = 0; ks < 4; ks++) {
                const int kc = ks * 2;
                uint32_t bh[2][4];
#pragma unroll
                for (int p = 0; p < 2; p++) {
                    uint32_t addr = st + MAT_A
                        + (uint32_t)(warp_n * 32 + p * 16 + b_noff) * PADB
                        + (uint32_t)(kc + b_ksub) * 16;
                    LDMX4(bh[p][0], bh[p][1], bh[p][2], bh[p][3], addr);
                }
#pragma unroll
                for (int mi = 0; mi < 4; mi++) {
                    uint32_t ah[4];
                    uint32_t addr = st
                        + (uint32_t)(warp_m * 64 + mi * 16 + a_moff) * PADB
                        + (uint32_t)(kc + a_ksub) * 16;
                    LDMX4(ah[0], ah[1], ah[2], ah[3], addr);
#pragma unroll
                    for (int p = 0; p < 2; p++) {
#pragma unroll
                        for (int q = 0; q < 2; q++) {
                            MMA_F16(acc[mi][p * 2 + q], ah, bh[p][q * 2], bh[p][q * 2 + 1]);
                        }
                    }
                }
            }
        }
#undef ISSUE_STAGE

        const int mbase = by * 128 + warp_m * 64 + (lane >> 2);
        const int nbase = n0 + warp_n * 32 + (lane & 3) * 2;
#pragma unroll
        for (int mi = 0; mi < 4; mi++) {
#pragma unroll
            for (int ni = 0; ni < 4; ni++) {
                const int n = nbase + ni * 8;
#pragma unroll
                for (int half = 0; half < 2; half++) {
                    const int m = mbase + mi * 16 + half * 8;
                    float vx = acc[mi][ni][half * 2 + 0];
                    float vy = acc[mi][ni][half * 2 + 1];
                    const size_t idx = (size_t)m * N + n;
                    if (emode == 1) {
                        float2 a = *(const float2*)(addmat + idx);
                        vx += a.x + bias[n];
                        vy += a.y + bias[n + 1];
                    } else if (emode >= 2) {
                        vx = ((vx > 0.f) ? vx : expm1f(vx)) * scale;
                        vy = ((vy > 0.f) ? vy : expm1f(vy)) * scale;
                        if (emode == 3) {
                            float2 c = *(const float2*)(Cmat + idx);
                            vx += c.x; vy += c.y;
                        }
                    }
                    float2 o; o.x = vx; o.y = vy;
                    *(float2*)(Cmat + idx) = o;
                }
            }
        }
    }
}

// ================= row LayerNorm -> fp16 hi =================
__global__ __launch_bounds__(128)
void ln_kernel(const float* __restrict__ in, __half* __restrict__ hi,
               const float* __restrict__ g, const float* __restrict__ b)
{
    const int row = blockIdx.x;
    const int tid = threadIdx.x;
    const int c = tid * 4;
    float4 v = *(const float4*)(in + (size_t)row * CDIM + c);
    float s  = v.x + v.y + v.z + v.w;
    float ss = v.x * v.x + v.y * v.y + v.z * v.z + v.w * v.w;
    __shared__ float rs[4], rss[4];
#pragma unroll
    for (int o = 16; o; o >>= 1) {
        s  += __shfl_down_sync(0xffffffffu, s,  o);
        ss += __shfl_down_sync(0xffffffffu, ss, o);
    }
    if ((tid & 31) == 0) { rs[tid >> 5] = s; rss[tid >> 5] = ss; }
    __syncthreads();
    float S  = rs[0] + rs[1] + rs[2] + rs[3];
    float SS = rss[0] + rss[1] + rss[2] + rss[3];
    float mu  = S * (1.f / CDIM);
    float var = SS * (1.f / CDIM) - mu * mu;
    float inv = rsqrtf(var + 1e-5f);
    float4 gv = *(const float4*)(g + c);
    float4 bv = *(const float4*)(b + c);
    ((uint2*)(hi + (size_t)row * CDIM))[tid] = pack4h(
        (v.x - mu) * inv * gv.x + bv.x,
        (v.y - mu) * inv * gv.y + bv.y,
        (v.z - mu) * inv * gv.z + bv.z,
        (v.w - mu) * inv * gv.w + bv.w);
}

// ================= s1/s2 =================
__global__ void s_kernel(const float* __restrict__ Wa)
{
    const int head = blockIdx.y;
    const int row = blockIdx.x * 8 + threadIdx.y;
    const int lane = threadIdx.x;
    const float* hr = g_h + (size_t)row * HDIM + head * CDIM;
    const float* wa = Wa + head * 2 * CDIM;
    float a = 0.f, bv = 0.f;
#pragma unroll
    for (int t = 0; t < 16; t++) {
        int c = lane + 32 * t;
        float hv = hr[c];
        a  = fmaf(hv, wa[c], a);
        bv = fmaf(hv, wa[CDIM + c], bv);
    }
#pragma unroll
    for (int o = 16; o; o >>= 1) {
        a  += __shfl_down_sync(0xffffffffu, a,  o);
        bv += __shfl_down_sync(0xffffffffu, bv, o);
    }
    if (lane == 0) { g_s1[head][row] = a; g_s2[head][row] = bv; }
}

// ================= rank phase 1 =================
__global__ __launch_bounds__(256)
void partial_rank_kernel()
{
    const int head = blockIdx.z;
    const int sl   = blockIdx.y;
    __shared__ float4 sh[256];
    sh[threadIdx.x] = ((const float4*)g_s2[head])[sl * 256 + threadIdx.x];
    __syncthreads();
    const int i = blockIdx.x * 256 + threadIdx.x;
    const float v = g_s2[head][i];
    int r = 0;
#pragma unroll 4
    for (int jj = 0; jj < 256; jj++) {
        float4 u = sh[jj];
        const int j = sl * 1024 + jj * 4;
        r += (u.x < v) || (u.x == v && j + 0 < i);
        r += (u.y < v) || (u.y == v && j + 1 < i);
        r += (u.z < v) || (u.z == v && j + 2 < i);
        r += (u.w < v) || (u.w == v && j + 3 < i);
    }
    g_rankpart[head][sl][i] = r;
}

// ================= rank phase 2 =================
__global__ __launch_bounds__(256)
void scatter_kernel()
{
    const int head = blockIdx.y;
    const int i = blockIdx.x * 256 + threadIdx.x;
    int r = 0;
#pragma unroll
    for (int sl = 0; sl < NSLICE; sl++) r += g_rankpart[head][sl][i];
    const float v = g_s2[head][i];
    g_sorted[head][r] = v;
    g_perm[head][r]   = i;
    g_wpos[head][r]   = expf(v);
    g_wneg[head][r]   = expf(0.01f * v);
}

// ================= fused local-prefix scan (single h pass) =====================
// Writes per-chunk exclusive prefixes Pneg16/Ppos16 (fp16) and chunk totals.
__global__ __launch_bounds__(128)
void local_scan_kernel()
{
    const int s = blockIdx.x, c = blockIdx.y, head = blockIdx.z;
    const int col = s * 128 + threadIdx.x;
    const int u0 = c * CHUNK;

    float accn = 0.f, accp = 0.f;
    const bool do_z = (s == 0 && threadIdx.x == 0);
    float zn = 0.f, zp = 0.f;

    if (c == NCHUNK - 1) {
        g_Pneg16[head][(size_t)NROWS * CDIM + col] = __float2half_rn(0.f);
        g_Ppos16[head][(size_t)NROWS * CDIM + col] = __float2half_rn(0.f);
        if (do_z) { g_Zpn[head][NROWS] = 0.f; g_Zpp[head][NROWS] = 0.f; }
    }

#pragma unroll 4
    for (int t = 0; t < CHUNK; t++) {
        const int u = u0 + t;
        const int r = g_perm[head][u];
        const float wp = g_wpos[head][u], wn = g_wneg[head][u];
        const float hv = g_h[(size_t)r * HDIM + head * CDIM + col];
        g_Pneg16[head][(size_t)u * CDIM + col] = __float2half_rn(accn);
        g_Ppos16[head][(size_t)u * CDIM + col] = __float2half_rn(accp);
        accn = fmaf(wn, hv, accn);
        accp = fmaf(wp, hv, accp);
        if (do_z) {
            g_Zpn[head][u] = zn;
            g_Zpp[head][u] = zp;
            zn += wn;
            zp += wp;
        }
    }
    g_cneg[head][c * CDIM + col] = accn;
    g_cpos[head][c * CDIM + col] = accp;
    if (do_z) { g_zcn[head][c] = zn; g_zcp[head][c] = zp; }
}

// ================= chunk offsets: offn (excl prefix), offp2 (incl suffix) ======
__global__ __launch_bounds__(512)
void chunk_scan_kernel()
{
    const int head = blockIdx.x;
    const int col = threadIdx.x;
    {
        float run = 0.f;
        for (int c0 = 0; c0 < NCHUNK; c0 += 8) {
            float v[8];
#pragma unroll
            for (int j = 0; j < 8; j++) v[j] = g_cneg[head][(c0 + j) * CDIM + col];
#pragma unroll
            for (int j = 0; j < 8; j++) {
                g_offn[head][(c0 + j) * CDIM + col] = run;
                run += v[j];
            }
        }
        g_offn[head][NCHUNK * CDIM + col] = run;
    }
    {
        float run = 0.f;
        g_offp2[head][NCHUNK * CDIM + col] = 0.f;
        for (int c0 = NCHUNK - 8; c0 >= 0; c0 -= 8) {
            float v[8];
#pragma unroll
            for (int j = 0; j < 8; j++) v[j] = g_cpos[head][(c0 + j) * CDIM + col];
#pragma unroll
            for (int j = 7; j >= 0; j--) {
                run += v[j];
                g_offp2[head][(c0 + j) * CDIM + col] = run;   // suffix incl chunk
            }
        }
    }
    if (col == 0) {
        float zr = 0.f;
        for (int c = 0; c < NCHUNK; c++) { g_zoffn[head][c] = zr; zr += g_zcn[head][c]; }
        g_zoffn[head][NCHUNK] = zr;
    } else if (col == 1) {
        float zr = 0.f;
        g_zoffp2[head][NCHUNK] = 0.f;
        for (int c = NCHUNK - 1; c >= 0; c--) { zr += g_zcp[head][c]; g_zoffp2[head][c] = zr; }
    }
}

// ================= combine: both heads per block (local+offset reconstruction) =
__global__ __launch_bounds__(128)
void combine_kernel(const float* __restrict__ ln2g, const float* __restrict__ ln2b)
{
    const int row = blockIdx.x;
    const int tid = threadIdx.x;
    __shared__ int sk[2];
    __shared__ float rs[4], rss[4];
    if (tid < 2) {
        const int hh = tid;
        float thr = -g_s1[hh][row];
        int lo = 0, hi = NROWS;
        while (lo < hi) {
            int mid = (lo + hi) >> 1;
            if (g_sorted[hh][mid] <= thr) lo = mid + 1; else hi = mid;
        }
        sk[hh] = lo;
    }
    __syncthreads();

    const int c4 = tid * 4;
    float4 xev = *(const float4*)(g_xe + (size_t)row * CDIM + c4);
    float4 gv = *(const float4*)(ln2g + c4);
    float4 bv = *(const float4*)(ln2b + c4);

#pragma unroll
    for (int head = 0; head < 2; head++) {
        const int k = sk[head];
        const int cc = k >> 7;                     // chunk index (64 when k==NROWS)
        const float s1v = g_s1[head][row];
        const float ap = expf(s1v);
        const float an = expf(0.01f * s1v);
        const float zpre = g_zoffn[head][cc] + g_Zpn[head][k];
        const float zsuf = g_zoffp2[head][cc] - g_Zpp[head][k];
        const float inv_den = 1.f / (ap * zsuf + an * zpre);

        uint2 pnu = *(const uint2*)(g_Pneg16[head] + (size_t)k * CDIM + c4);
        uint2 ppu = *(const uint2*)(g_Ppos16[head] + (size_t)k * CDIM + c4);
        float2 pn0 = __half22float2(*(__half2*)&pnu.x);
        float2 pn1 = __half22float2(*(__half2*)&pnu.y);
        float2 pp0 = __half22float2(*(__half2*)&ppu.x);
        float2 pp1 = __half22float2(*(__half2*)&ppu.y);
        float4 onv = *(const float4*)(g_offn[head]  + (size_t)cc * CDIM + c4);
        float4 opv = *(const float4*)(g_offp2[head] + (size_t)cc * CDIM + c4);

        float vx = (ap * (opv.x - pp0.x) + an * (onv.x + pn0.x)) * inv_den + xev.x;
        float vy = (ap * (opv.y - pp0.y) + an * (onv.y + pn0.y)) * inv_den + xev.y;
        float vz = (ap * (opv.z - pp1.x) + an * (onv.z + pn1.x)) * inv_den + xev.z;
        float vw = (ap * (opv.w - pp1.y) + an * (onv.w + pn1.y)) * inv_den + xev.w;

        float s  = vx + vy + vz + vw;
        float ss = vx * vx + vy * vy + vz * vz + vw * vw;
#pragma unroll
        for (int o = 16; o; o >>= 1) {
            s  += __shfl_down_sync(0xffffffffu, s,  o);
            ss += __shfl_down_sync(0xffffffffu, ss, o);
        }
        if ((tid & 31) == 0) { rs[tid >> 5] = s; rss[tid >> 5] = ss; }
        __syncthreads();
        float S  = rs[0] + rs[1] + rs[2] + rs[3];
        float SS = rss[0] + rss[1] + rss[2] + rss[3];
        float mu  = S * (1.f / CDIM);
        float var = SS * (1.f / CDIM) - mu * mu;
        float inv = rsqrtf(var + 1e-5f);
        ((uint2*)(g_att_h[head] + (size_t)row * CDIM))[tid] = pack4h(
            (vx - mu) * inv * gv.x + bv.x,
            (vy - mu) * inv * gv.y + bv.y,
            (vz - mu) * inv * gv.z + bv.z,
            (vw - mu) * inv * gv.w + bv.w);
        __syncthreads();
    }
}

// ================= launch =================
extern "C" void kernel_launch(void* const* d_in, const int* in_sizes, int n_in,
                              void* d_out, int out_size)
{
    const float* x     = (const float*)d_in[0];
    const float* enc   = (const float*)d_in[1];
    const float* W_enc = (const float*)d_in[2];
    const float* b_enc = (const float*)d_in[3];
    const float* ln1g  = (const float*)d_in[4];
    const float* ln1b  = (const float*)d_in[5];
    const float* ln2g  = (const float*)d_in[6];
    const float* ln2b  = (const float*)d_in[7];
    const float* W0    = (const float*)d_in[8];
    const float* W1    = (const float*)d_in[9];
    const float* Wa    = (const float*)d_in[10];
    float* out = (float*)d_out;

    static int attr_done = 0;
    if (!attr_done) {
        cudaFuncSetAttribute(gemm_f16, cudaFuncAttributeMaxDynamicSharedMemorySize, SMEM_GEMM);
        attr_done = 1;
    }

    void *p_xe, *p_h;
    cudaGetSymbolAddress(&p_xe, g_xe);
    cudaGetSymbolAddress(&p_h,  g_h);
    float* xe = (float*)p_xe;
    float* h  = (float*)p_h;

    void *p_ench, *p_wench, *p_xnh, *p_atth, *p_w0h, *p_w1h;
    cudaGetSymbolAddress(&p_ench,  g_enc_h);
    cudaGetSymbolAddress(&p_wench, g_wenc_h);
    cudaGetSymbolAddress(&p_xnh,   g_xn_h);
    cudaGetSymbolAddress(&p_atth,  g_att_h);
    cudaGetSymbolAddress(&p_w0h,   g_w0_h);
    cudaGetSymbolAddress(&p_w1h,   g_w1_h);
    __half* ench  = (__half*)p_ench;
    __half* wench = (__half*)p_wench;
    __half* xnh   = (__half*)p_xnh;
    __half* atth  = (__half*)p_atth;
    __half* w0h   = (__half*)p_w0h;
    __half* w1h   = (__half*)p_w1h;

    dim3 ggrid(2, NROWS / 128);             // (2, 64) = 128 CTAs
    dim3 scan_grid(CDIM / 128, NCHUNK, 2);

    convert_all<<<(N4_ALL + 255) / 256, 256>>>(enc, W_enc, W0, W1);

    // 1) xe = x + enc @ W_enc^T + b_enc
    gemm_f16<<<ggrid, 512, SMEM_GEMM>>>(ench, wench, xe,
                                        NROWS, CDIM, EDIM, 1, x, b_enc, 1.f,
                                        1, nullptr, nullptr);
    // 2) xn = LN1(xe)
    ln_kernel<<<NROWS, 128>>>(xe, xnh, ln1g, ln1b);

    // 3) h_both = xn @ [W0_0; W0_1]^T
    gemm_f16<<<ggrid, 512, SMEM_GEMM>>>(xnh, w0h, h,
                                        NROWS, HDIM, CDIM, 0, nullptr, nullptr, 1.f,
                                        2, nullptr, nullptr);

    // 4-7) merged per-head attention pipeline (single h pass for scans)
    s_kernel<<<dim3(NROWS / 8, 2), dim3(32, 8)>>>(Wa);
    partial_rank_kernel<<<dim3(NROWS / 256, NSLICE, 2), 256>>>();
    scatter_kernel<<<dim3(NROWS / 256, 2), 256>>>();
    local_scan_kernel<<<scan_grid, 128>>>();
    chunk_scan_kernel<<<2, 512>>>();
    combine_kernel<<<NROWS, 128>>>(ln2g, ln2b);

    // 8) out = elu(att0 @ W1_0^T)/2 + elu(att1 @ W1_1^T)/2  (fused single launch)
    gemm_f16<<<ggrid, 512, SMEM_GEMM>>>(atth, w1h, out,
                                        NROWS, CDIM, CDIM, 2, nullptr, nullptr, 0.5f,
                                        1, atth + (size_t)NROWS * CDIM,
                                        w1h + (size_t)CDIM * CDIM);
}